// round 1
// baseline (speedup 1.0000x reference)
#include <cuda_runtime.h>

// Problem shape (fixed by the reference): inputs (128, 64, 64, 32) fp32
// => B=128 batches, N=64 rows per batch, D=64*32=2048 features per row.
//
// loss = mean_b( || sum_n att[b,n,:] ||^2 ) - mean_b( sum_n <att_n, att_n> )
// where att = x / max(||x||_2, 1e-12) row-wise.

#define BB   128
#define NN   64
#define DD   2048
#define ROWS (BB * NN)
#define T1   256           // threads for k1/k2
#define EPS  1e-12

// Scratch (allocation-free: __device__ globals). All fully overwritten every
// call -> no init kernel needed, deterministic (no atomics anywhere).
__device__ float g_inv[ROWS];     // 1 / max(||row||, eps)
__device__ float g_t2row[ROWS];   // sumsq * inv^2  (diag term per row)
__device__ float g_t1[BB];        // per-batch || sum_n att_n ||^2
__device__ float g_t2b[BB];       // per-batch sum of diag terms

// ---------------------------------------------------------------------------
// Kernel 1: per-row sum of squares -> inverse norm + diag term.
// One block per row. 256 threads x 8 floats (2x float4) = 2048 floats.
// ---------------------------------------------------------------------------
__global__ __launch_bounds__(T1) void k1_norms(const float* __restrict__ x) {
    const int row = blockIdx.x;
    const int t   = threadIdx.x;
    const float4* p = reinterpret_cast<const float4*>(x + (size_t)row * DD);

    float4 a = p[t];
    float4 b = p[t + T1];
    float ss = a.x * a.x + a.y * a.y + a.z * a.z + a.w * a.w
             + b.x * b.x + b.y * b.y + b.z * b.z + b.w * b.w;

    // warp reduce
    #pragma unroll
    for (int o = 16; o; o >>= 1) ss += __shfl_xor_sync(0xffffffffu, ss, o);

    __shared__ float ws[T1 / 32];
    if ((t & 31) == 0) ws[t >> 5] = ss;
    __syncthreads();

    if (t < (T1 / 32)) {
        float v = ws[t];
        #pragma unroll
        for (int o = (T1 / 64); o; o >>= 1) v += __shfl_xor_sync(0xffu, v, o);
        if (t == 0) {
            double sd  = (double)v;
            double nrm = sqrt(sd);
            if (nrm < EPS) nrm = EPS;
            g_inv[row]   = (float)(1.0 / nrm);
            g_t2row[row] = (float)(sd / (nrm * nrm));  // == 1 unless degenerate
        }
    }
}

// ---------------------------------------------------------------------------
// Kernel 2: per-batch weighted column sums s[d] = sum_n x[b,n,d]*inv[b,n],
// then reduce sum_d s[d]^2 -> g_t1[b]. Also reduce the 64 diag terms -> g_t2b.
// One block per batch, 256 threads, each owns 8 d-columns (2x float4).
// Input should be L2-resident from k1's streaming pass.
// ---------------------------------------------------------------------------
__global__ __launch_bounds__(T1) void k2_colsum(const float* __restrict__ x) {
    const int b = blockIdx.x;
    const int t = threadIdx.x;

    __shared__ float s_inv[NN];
    if (t < NN) s_inv[t] = g_inv[b * NN + t];
    __syncthreads();

    const float4* p = reinterpret_cast<const float4*>(x + (size_t)b * NN * DD);
    float4 s0 = make_float4(0.f, 0.f, 0.f, 0.f);
    float4 s1 = make_float4(0.f, 0.f, 0.f, 0.f);

    // Independent loads across n (no dependency chain on the loads) -> high MLP.
    #pragma unroll 8
    for (int n = 0; n < NN; n++) {
        const float w  = s_inv[n];
        const float4 a = p[n * (DD / 4) + t];
        const float4 c = p[n * (DD / 4) + t + T1];
        s0.x = fmaf(w, a.x, s0.x); s0.y = fmaf(w, a.y, s0.y);
        s0.z = fmaf(w, a.z, s0.z); s0.w = fmaf(w, a.w, s0.w);
        s1.x = fmaf(w, c.x, s1.x); s1.y = fmaf(w, c.y, s1.y);
        s1.z = fmaf(w, c.z, s1.z); s1.w = fmaf(w, c.w, s1.w);
    }

    float loc = s0.x * s0.x + s0.y * s0.y + s0.z * s0.z + s0.w * s0.w
              + s1.x * s1.x + s1.y * s1.y + s1.z * s1.z + s1.w * s1.w;

    // diag term for this batch (threads < 64 contribute)
    float t2v = (t < NN) ? g_t2row[b * NN + t] : 0.f;

    // reduce both values
    #pragma unroll
    for (int o = 16; o; o >>= 1) {
        loc += __shfl_xor_sync(0xffffffffu, loc, o);
        t2v += __shfl_xor_sync(0xffffffffu, t2v, o);
    }
    __shared__ float w1[T1 / 32], w2[T1 / 32];
    if ((t & 31) == 0) { w1[t >> 5] = loc; w2[t >> 5] = t2v; }
    __syncthreads();
    if (t < (T1 / 32)) {
        float v1 = w1[t], v2 = w2[t];
        #pragma unroll
        for (int o = (T1 / 64); o; o >>= 1) {
            v1 += __shfl_xor_sync(0xffu, v1, o);
            v2 += __shfl_xor_sync(0xffu, v2, o);
        }
        if (t == 0) { g_t1[b] = v1; g_t2b[b] = v2; }
    }
}

// ---------------------------------------------------------------------------
// Kernel 3: deterministic final combine in double (the loss is a cancellation
// of two ~64-magnitude terms; keep it precise).
// ---------------------------------------------------------------------------
__global__ void k3_final(float* __restrict__ out) {
    if (threadIdx.x == 0 && blockIdx.x == 0) {
        double t1 = 0.0, t2 = 0.0;
        for (int i = 0; i < BB; i++) { t1 += (double)g_t1[i]; t2 += (double)g_t2b[i]; }
        out[0] = (float)((t1 - t2) / (double)BB);
    }
}

extern "C" void kernel_launch(void* const* d_in, const int* in_sizes, int n_in,
                              void* d_out, int out_size) {
    (void)in_sizes; (void)n_in; (void)out_size;
    const float* x = (const float*)d_in[0];
    float* out = (float*)d_out;

    k1_norms <<<ROWS, T1>>>(x);
    k2_colsum<<<BB,   T1>>>(x);
    k3_final <<<1,    32>>>(out);
}

// round 3
// speedup vs baseline: 1.5850x; 1.5850x over previous
#include <cuda_runtime.h>

// inputs (128, 64, 64, 32) fp32 => B=128, N=64 rows/batch, D=2048 feat/row.
// loss = mean_b( || sum_n att[b,n,:] ||^2 ) - mean_b( sum_n <att_n,att_n> )
// att = x / max(||x||, 1e-12) row-wise.

#define BB    128
#define NN    64
#define DD    2048
#define ROWS  (BB * NN)          // 8192
#define EPS   1e-12

#define K1_WARPS 8               // warps per block in k1
#define K1_BLOCKS (ROWS / K1_WARPS)   // 1024

#define SPLIT 4                  // blocks per batch in k2 (split along D)
#define K2_T  128                // threads per k2 block; SPLIT*K2_T = 512 float4 cols
#define K2_BLOCKS (BB * SPLIT)   // 512

// Scratch: __device__ globals (allocation-free). All overwritten each call.
__device__ float g_inv[ROWS];          // 1/max(||row||,eps)
__device__ float g_t2row[ROWS];       // sumsq*inv^2 (diag term, ==1 unless degenerate)
__device__ float g_t1p[K2_BLOCKS];    // partial sum_d s_d^2 per (batch, d-chunk)

// ---------------------------------------------------------------------------
// k1: warp-per-row sum of squares. 16 independent float4 loads/thread,
// warp-shuffle reduce only — no smem, no __syncthreads.
// ---------------------------------------------------------------------------
__global__ __launch_bounds__(K1_WARPS * 32) void k1_norms(const float* __restrict__ x) {
    const int warp = (blockIdx.x * K1_WARPS) + (threadIdx.x >> 5);  // row id
    const int lane = threadIdx.x & 31;
    const float4* p = reinterpret_cast<const float4*>(x + (size_t)warp * DD);

    float4 v[16];
    #pragma unroll
    for (int i = 0; i < 16; i++) v[i] = p[lane + 32 * i];   // front-batched loads

    float s0 = 0.f, s1 = 0.f, s2 = 0.f, s3 = 0.f;
    #pragma unroll
    for (int i = 0; i < 16; i += 4) {
        s0 += v[i+0].x*v[i+0].x + v[i+0].y*v[i+0].y + v[i+0].z*v[i+0].z + v[i+0].w*v[i+0].w;
        s1 += v[i+1].x*v[i+1].x + v[i+1].y*v[i+1].y + v[i+1].z*v[i+1].z + v[i+1].w*v[i+1].w;
        s2 += v[i+2].x*v[i+2].x + v[i+2].y*v[i+2].y + v[i+2].z*v[i+2].z + v[i+2].w*v[i+2].w;
        s3 += v[i+3].x*v[i+3].x + v[i+3].y*v[i+3].y + v[i+3].z*v[i+3].z + v[i+3].w*v[i+3].w;
    }
    float ss = (s0 + s1) + (s2 + s3);

    #pragma unroll
    for (int o = 16; o; o >>= 1) ss += __shfl_xor_sync(0xffffffffu, ss, o);

    if (lane == 0) {
        double sd  = (double)ss;
        double nrm = sqrt(sd);
        if (nrm < EPS) nrm = EPS;
        g_inv[warp]   = (float)(1.0 / nrm);
        g_t2row[warp] = (float)(sd / (nrm * nrm));
    }
}

// ---------------------------------------------------------------------------
// k2: per-batch weighted column sums, split over SPLIT d-chunks per batch.
// block (b, c): thread t owns float4 column c*K2_T + t; loops n=0..63.
// Writes partial sum_d s_d^2 to g_t1p. Input is L2-resident after k1.
// ---------------------------------------------------------------------------
__global__ __launch_bounds__(K2_T) void k2_colsum(const float* __restrict__ x) {
    const int b = blockIdx.x / SPLIT;
    const int c = blockIdx.x % SPLIT;
    const int t = threadIdx.x;

    __shared__ float s_inv[NN];
    if (t < NN) s_inv[t] = g_inv[b * NN + t];
    __syncthreads();

    const float4* p = reinterpret_cast<const float4*>(x + (size_t)b * NN * DD)
                      + c * K2_T + t;                 // this thread's column
    float4 s = make_float4(0.f, 0.f, 0.f, 0.f);

    #pragma unroll 16
    for (int n = 0; n < NN; n++) {
        const float  w = s_inv[n];
        const float4 a = p[n * (DD / 4)];
        s.x = fmaf(w, a.x, s.x); s.y = fmaf(w, a.y, s.y);
        s.z = fmaf(w, a.z, s.z); s.w = fmaf(w, a.w, s.w);
    }

    float loc = s.x*s.x + s.y*s.y + s.z*s.z + s.w*s.w;
    #pragma unroll
    for (int o = 16; o; o >>= 1) loc += __shfl_xor_sync(0xffffffffu, loc, o);

    __shared__ float ws[K2_T / 32];
    if ((t & 31) == 0) ws[t >> 5] = loc;
    __syncthreads();
    if (t == 0) {
        float v = ws[0];
        #pragma unroll
        for (int i = 1; i < K2_T / 32; i++) v += ws[i];
        g_t1p[blockIdx.x] = v;
    }
}

// ---------------------------------------------------------------------------
// k3: final combine. One block, double accumulators (protects the t1-t2
// cancellation), deterministic reduction order.
// ---------------------------------------------------------------------------
__global__ __launch_bounds__(256) void k3_final(float* __restrict__ out) {
    const int t = threadIdx.x;
    double acc = 0.0;

    for (int i = t; i < K2_BLOCKS; i += 256) acc += (double)g_t1p[i];
    for (int i = t; i < ROWS;      i += 256) acc -= (double)g_t2row[i];

    // block reduce in double via shared memory
    __shared__ double sd[256];
    sd[t] = acc;
    __syncthreads();
    #pragma unroll
    for (int o = 128; o; o >>= 1) {
        if (t < o) sd[t] += sd[t + o];
        __syncthreads();
    }
    if (t == 0) out[0] = (float)(sd[0] / (double)BB);
}

extern "C" void kernel_launch(void* const* d_in, const int* in_sizes, int n_in,
                              void* d_out, int out_size) {
    (void)in_sizes; (void)n_in; (void)out_size;
    const float* x = (const float*)d_in[0];
    float* out = (float*)d_out;

    k1_norms <<<K1_BLOCKS, K1_WARPS * 32>>>(x);
    k2_colsum<<<K2_BLOCKS, K2_T>>>(x);
    k3_final <<<1, 256>>>(out);
}

// round 5
// speedup vs baseline: 1.6520x; 1.0423x over previous
#include <cuda_runtime.h>

// inputs (128, 64, 64, 32) fp32 => B=128, N=64 rows/batch, D=2048 feat/row.
// loss = mean_b( || sum_n att[b,n,:] ||^2 ) - mean_b( sum_n <att_n,att_n> )
// att = x / max(||x||, 1e-12) row-wise.

#define BB    128
#define NN    64
#define DD    2048
#define ROWS  (BB * NN)          // 8192
#define EPS   1e-12

#define K1_T      128                 // 4 warps per block, warp-per-row
#define K1_WPB    4
#define K1_BLOCKS (ROWS / K1_WPB)     // 2048

#define SPLIT     4                   // d-chunks per batch in k2
#define K2_T      128
#define K2_BLOCKS (BB * SPLIT)        // 512

// Scratch (__device__ globals; allocation-free). All overwritten per call.
__device__ float g_inv[ROWS];         // 1/max(||row||,eps)
__device__ float g_t2row[ROWS];       // sumsq*inv^2 (diag term)
__device__ float g_t1p[K2_BLOCKS];    // partial sum_d s_d^2 per (batch,chunk)
__device__ unsigned int g_done;       // finisher election; reset by finisher

// ---------------------------------------------------------------------------
// k1: warp-per-row sum of squares. Loads issued in batches of 4 LDG.128
// (outer loop NOT unrolled) to keep MLP_p1 ~= 4: avoids the cross-CTA
// L1tex-queue contention spread that capped DRAM BW at ~58%.
// ---------------------------------------------------------------------------
__global__ __launch_bounds__(K1_T) void k1_norms(const float* __restrict__ x) {
    const int row  = blockIdx.x * K1_WPB + (threadIdx.x >> 5);
    const int lane = threadIdx.x & 31;
    const float4* p = reinterpret_cast<const float4*>(x + (size_t)row * DD) + lane;

    float s0 = 0.f, s1 = 0.f, s2 = 0.f, s3 = 0.f;
    #pragma unroll 1
    for (int i = 0; i < 4; i++) {
        const float4 a = p[i * 128 +  0];
        const float4 b = p[i * 128 + 32];
        const float4 c = p[i * 128 + 64];
        const float4 d = p[i * 128 + 96];
        s0 += a.x*a.x + a.y*a.y + a.z*a.z + a.w*a.w;
        s1 += b.x*b.x + b.y*b.y + b.z*b.z + b.w*b.w;
        s2 += c.x*c.x + c.y*c.y + c.z*c.z + c.w*c.w;
        s3 += d.x*d.x + d.y*d.y + d.z*d.z + d.w*d.w;
    }
    float ss = (s0 + s1) + (s2 + s3);

    #pragma unroll
    for (int o = 16; o; o >>= 1) ss += __shfl_xor_sync(0xffffffffu, ss, o);

    if (lane == 0) {
        double sd  = (double)ss;
        double nrm = sqrt(sd);
        if (nrm < EPS) nrm = EPS;
        g_inv[row]   = (float)(1.0 / nrm);
        g_t2row[row] = (float)(sd / (nrm * nrm));
    }
}

// ---------------------------------------------------------------------------
// k2: per-batch weighted column sums split over SPLIT d-chunks (L2-resident
// reread). Last-finishing block performs the final double-precision combine
// (threadfence-reduction pattern) -> no separate k3 launch.
// ---------------------------------------------------------------------------
__global__ __launch_bounds__(K2_T) void k2_colsum(const float* __restrict__ x,
                                                  float* __restrict__ out) {
    const int b = blockIdx.x / SPLIT;
    const int c = blockIdx.x % SPLIT;
    const int t = threadIdx.x;

    __shared__ float s_inv[NN];
    if (t < NN) s_inv[t] = g_inv[b * NN + t];
    __syncthreads();

    const float4* p = reinterpret_cast<const float4*>(x + (size_t)b * NN * DD)
                      + c * K2_T + t;
    float4 s = make_float4(0.f, 0.f, 0.f, 0.f);

    #pragma unroll 8
    for (int n = 0; n < NN; n++) {
        const float  w = s_inv[n];
        const float4 a = p[n * (DD / 4)];
        s.x = fmaf(w, a.x, s.x); s.y = fmaf(w, a.y, s.y);
        s.z = fmaf(w, a.z, s.z); s.w = fmaf(w, a.w, s.w);
    }

    float loc = s.x*s.x + s.y*s.y + s.z*s.z + s.w*s.w;
    #pragma unroll
    for (int o = 16; o; o >>= 1) loc += __shfl_xor_sync(0xffffffffu, loc, o);

    __shared__ float ws[K2_T / 32];
    if ((t & 31) == 0) ws[t >> 5] = loc;
    __syncthreads();

    __shared__ bool s_last;
    if (t == 0) {
        float v = ws[0];
        #pragma unroll
        for (int i = 1; i < K2_T / 32; i++) v += ws[i];
        g_t1p[blockIdx.x] = v;
        __threadfence();
        unsigned int old = atomicAdd(&g_done, 1u);
        s_last = (old == (unsigned int)(K2_BLOCKS - 1));
    }
    __syncthreads();
    if (!s_last) return;

    // ---- finisher: deterministic final combine in double ----
    __threadfence();   // acquire all blocks' g_t1p / k1's g_t2row
    double acc = 0.0;
    for (int i = t; i < K2_BLOCKS; i += K2_T) acc += (double)g_t1p[i];
    for (int i = t; i < ROWS;      i += K2_T) acc -= (double)g_t2row[i];

    __shared__ double sd[K2_T];
    sd[t] = acc;
    __syncthreads();
    #pragma unroll
    for (int o = K2_T / 2; o; o >>= 1) {
        if (t < o) sd[t] += sd[t + o];
        __syncthreads();
    }
    if (t == 0) {
        out[0] = (float)(sd[0] / (double)BB);
        g_done = 0;    // reset for next graph replay
    }
}

extern "C" void kernel_launch(void* const* d_in, const int* in_sizes, int n_in,
                              void* d_out, int out_size) {
    (void)in_sizes; (void)n_in; (void)out_size;
    const float* x = (const float*)d_in[0];
    float* out = (float*)d_out;

    k1_norms <<<K1_BLOCKS, K1_T>>>(x);
    k2_colsum<<<K2_BLOCKS, K2_T>>>(x, out);
}

// round 6
// speedup vs baseline: 1.7487x; 1.0585x over previous
#include <cuda_runtime.h>

// inputs (128, 64, 64, 32) fp32 => B=128, N=64 rows/batch, D=2048.
// loss = mean_b( || sum_n att[b,n,:] ||^2 - sum_n <att_n,att_n> ),
// att = x / max(||x||,1e-12) row-wise.
//
// Single fused persistent kernel: block b owns batch b.
//  Phase A: row norms -> smem (streams 512 KB from DRAM)
//  Phase B: weighted column sums (re-reads same 512 KB, L2-hot)
// Last block combines the 128 per-batch partials in double.

#define BB   128
#define NN   64
#define DD   2048
#define NT   512          // threads per block (16 warps)
#define EPS  1e-12

__device__ double       g_part[BB];   // per-batch t1_b - t2_b
__device__ unsigned int g_done;       // finisher election (reset by finisher)

__global__ __launch_bounds__(NT) void fused_loss(const float* __restrict__ x,
                                                 float* __restrict__ out) {
    const int b    = blockIdx.x;
    const int t    = threadIdx.x;
    const int warp = t >> 5;
    const int lane = t & 31;
    const float* base = x + (size_t)b * NN * DD;

    __shared__ float s_inv[NN];
    __shared__ float s_diag[NN];

    // ---------------- Phase A: per-row sum of squares (DRAM stream) --------
    // 16 warps x 4 rows each. Per row: 16 float4 loads/lane, stride 32.
    #pragma unroll
    for (int r = 0; r < 4; r++) {
        const int row = warp * 4 + r;
        const float4* p = reinterpret_cast<const float4*>(base + (size_t)row * DD) + lane;
        float s0 = 0.f, s1 = 0.f, s2 = 0.f, s3 = 0.f;
        #pragma unroll
        for (int i = 0; i < 16; i += 4) {
            const float4 a = p[(i + 0) * 32];
            const float4 c = p[(i + 1) * 32];
            const float4 d = p[(i + 2) * 32];
            const float4 e = p[(i + 3) * 32];
            s0 += a.x*a.x + a.y*a.y + a.z*a.z + a.w*a.w;
            s1 += c.x*c.x + c.y*c.y + c.z*c.z + c.w*c.w;
            s2 += d.x*d.x + d.y*d.y + d.z*d.z + d.w*d.w;
            s3 += e.x*e.x + e.y*e.y + e.z*e.z + e.w*e.w;
        }
        float ss = (s0 + s1) + (s2 + s3);
        #pragma unroll
        for (int o = 16; o; o >>= 1) ss += __shfl_xor_sync(0xffffffffu, ss, o);
        if (lane == 0) {
            double sd  = (double)ss;
            double nrm = sqrt(sd);
            if (nrm < EPS) nrm = EPS;
            s_inv[row]  = (float)(1.0 / nrm);
            s_diag[row] = (float)(sd / (nrm * nrm));
        }
    }
    __syncthreads();

    // ---------------- Phase B: weighted column sums (L2-hot reread) --------
    // Thread t owns float4 column t (DD/4 = 512 = NT columns).
    const float4* q = reinterpret_cast<const float4*>(base) + t;
    float4 s = make_float4(0.f, 0.f, 0.f, 0.f);
    #pragma unroll 8
    for (int n = 0; n < NN; n++) {
        const float  w = s_inv[n];
        const float4 a = q[n * (DD / 4)];
        s.x = fmaf(w, a.x, s.x); s.y = fmaf(w, a.y, s.y);
        s.z = fmaf(w, a.z, s.z); s.w = fmaf(w, a.w, s.w);
    }
    float v1 = s.x*s.x + s.y*s.y + s.z*s.z + s.w*s.w;   // partial ||s||^2
    float v2 = (t < NN) ? s_diag[t] : 0.f;              // diag terms

    // block reduce both values
    #pragma unroll
    for (int o = 16; o; o >>= 1) {
        v1 += __shfl_xor_sync(0xffffffffu, v1, o);
        v2 += __shfl_xor_sync(0xffffffffu, v2, o);
    }
    __shared__ float w1[NT / 32], w2[NT / 32];
    if (lane == 0) { w1[warp] = v1; w2[warp] = v2; }
    __syncthreads();

    __shared__ bool s_last;
    if (t == 0) {
        float t1 = 0.f, t2 = 0.f;
        #pragma unroll
        for (int i = 0; i < NT / 32; i++) { t1 += w1[i]; t2 += w2[i]; }
        g_part[b] = (double)t1 - (double)t2;
        __threadfence();
        unsigned int old = atomicAdd(&g_done, 1u);
        s_last = (old == (unsigned int)(BB - 1));
    }
    __syncthreads();
    if (!s_last) return;

    // ---------------- Finisher: combine 128 partials in double ------------
    __threadfence();
    double acc = (t < BB) ? g_part[t] : 0.0;
    __shared__ double sd[128];
    if (t < 128) sd[t] = acc;
    __syncthreads();
    #pragma unroll
    for (int o = 64; o; o >>= 1) {
        if (t < o) sd[t] += sd[t + o];
        __syncthreads();
    }
    if (t == 0) {
        out[0] = (float)(sd[0] / (double)BB);
        g_done = 0;   // reset for next graph replay
    }
}

extern "C" void kernel_launch(void* const* d_in, const int* in_sizes, int n_in,
                              void* d_out, int out_size) {
    (void)in_sizes; (void)n_in; (void)out_size;
    const float* x = (const float*)d_in[0];
    float* out = (float*)d_out;
    fused_loss<<<BB, NT>>>(x, out);
}

// round 7
// speedup vs baseline: 1.9961x; 1.1415x over previous
#include <cuda_runtime.h>

// inputs (128, 64, 64, 32) fp32 => B=128, N=64 rows/batch, D=2048.
// loss = mean_b( || sum_n att[b,n,:] ||^2 - sum_n <att_n,att_n> ),
// att = x / max(||x||,1e-12) row-wise.
//
// Fused kernel, block b owns batch b, 1024 threads:
//  Phase A: 32 warps x 2 rows -> row norms in smem
//  Phase B: 2 threads per float4-column, each sums 32 rows; combine via smem
// Last block combines the 128 per-batch partials in double.

#define BB   128
#define NN   64
#define DD   2048
#define NF4  (DD / 4)     // 512 float4 columns
#define NT   1024         // 32 warps
#define EPS  1e-12

__device__ double       g_part[BB];
__device__ unsigned int g_done;

__global__ __launch_bounds__(NT) void fused_loss(const float* __restrict__ x,
                                                 float* __restrict__ out) {
    const int b    = blockIdx.x;
    const int t    = threadIdx.x;
    const int warp = t >> 5;
    const int lane = t & 31;
    const float* base = x + (size_t)b * NN * DD;
    const float4* base4 = reinterpret_cast<const float4*>(base);

    __shared__ float  s_inv[NN];
    __shared__ float  s_diag[NN];
    __shared__ float4 s_half[NF4];          // upper-half partial column sums
    __shared__ float  w1[NT / 32], w2[NT / 32];

    // ---------------- Phase A: row sum-of-squares (32 warps x 2 rows) ------
    #pragma unroll
    for (int r = 0; r < 2; r++) {
        const int row = warp * 2 + r;
        const float4* p = base4 + row * NF4 + lane;
        float s0 = 0.f, s1 = 0.f, s2 = 0.f, s3 = 0.f;
        #pragma unroll
        for (int i = 0; i < 16; i += 4) {
            const float4 a = p[(i + 0) * 32];
            const float4 c = p[(i + 1) * 32];
            const float4 d = p[(i + 2) * 32];
            const float4 e = p[(i + 3) * 32];
            s0 += a.x*a.x + a.y*a.y + a.z*a.z + a.w*a.w;
            s1 += c.x*c.x + c.y*c.y + c.z*c.z + c.w*c.w;
            s2 += d.x*d.x + d.y*d.y + d.z*d.z + d.w*d.w;
            s3 += e.x*e.x + e.y*e.y + e.z*e.z + e.w*e.w;
        }
        float ss = (s0 + s1) + (s2 + s3);
        #pragma unroll
        for (int o = 16; o; o >>= 1) ss += __shfl_xor_sync(0xffffffffu, ss, o);
        if (lane == 0) {
            double sd  = (double)ss;
            double nrm = sqrt(sd);
            if (nrm < EPS) nrm = EPS;
            s_inv[row]  = (float)(1.0 / nrm);
            s_diag[row] = (float)(sd / (nrm * nrm));
        }
    }
    __syncthreads();

    // ---------------- Phase B: weighted column sums --------------------------
    // Threads t and t+512 share column (t & 511); each sums a 32-row half.
    const int col  = t & (NF4 - 1);
    const int half = t >> 9;                       // 0 or 1
    const float4* q = base4 + (size_t)half * 32 * NF4 + col;
    const float* wv = s_inv + half * 32;

    float4 s = make_float4(0.f, 0.f, 0.f, 0.f);
    #pragma unroll 8
    for (int n = 0; n < 32; n++) {
        const float  w = wv[n];
        const float4 a = q[n * NF4];
        s.x = fmaf(w, a.x, s.x); s.y = fmaf(w, a.y, s.y);
        s.z = fmaf(w, a.z, s.z); s.w = fmaf(w, a.w, s.w);
    }

    if (half == 1) s_half[col] = s;
    __syncthreads();

    float v1 = 0.f;
    if (half == 0) {
        const float4 hsum = s_half[col];
        const float sx = s.x + hsum.x, sy = s.y + hsum.y;
        const float sz = s.z + hsum.z, sw = s.w + hsum.w;
        v1 = sx*sx + sy*sy + sz*sz + sw*sw;
    }
    float v2 = (t < NN) ? s_diag[t] : 0.f;

    #pragma unroll
    for (int o = 16; o; o >>= 1) {
        v1 += __shfl_xor_sync(0xffffffffu, v1, o);
        v2 += __shfl_xor_sync(0xffffffffu, v2, o);
    }
    if (lane == 0) { w1[warp] = v1; w2[warp] = v2; }
    __syncthreads();

    __shared__ bool s_last;
    if (t == 0) {
        float t1 = 0.f, t2 = 0.f;
        #pragma unroll
        for (int i = 0; i < NT / 32; i++) { t1 += w1[i]; t2 += w2[i]; }
        g_part[b] = (double)t1 - (double)t2;
        __threadfence();
        unsigned int old = atomicAdd(&g_done, 1u);
        s_last = (old == (unsigned int)(BB - 1));
    }
    __syncthreads();
    if (!s_last) return;

    // ---------------- Finisher: combine partials in double -----------------
    __threadfence();
    __shared__ double sd[128];
    if (t < BB) sd[t] = g_part[t];
    __syncthreads();
    #pragma unroll
    for (int o = 64; o; o >>= 1) {
        if (t < o) sd[t] += sd[t + o];
        __syncthreads();
    }
    if (t == 0) {
        out[0] = (float)(sd[0] / (double)BB);
        g_done = 0;
    }
}

extern "C" void kernel_launch(void* const* d_in, const int* in_sizes, int n_in,
                              void* d_out, int out_size) {
    (void)in_sizes; (void)n_in; (void)out_size;
    const float* x = (const float*)d_in[0];
    float* out = (float*)d_out;
    fused_loss<<<BB, NT>>>(x, out);
}